// round 10
// baseline (speedup 1.0000x reference)
#include <cuda_runtime.h>
#include <cstdint>

// Problem constants
#define P_DIM 64
#define B_DIM 256
#define H_DIM 512
#define IN_DIM 2
#define PB (P_DIM * B_DIM)      // 16384 fused batch rows

// Tiling: CTA = 128 rows x 256 gate-cols (4 gates x 64 h), 8 warps of 64x64
#define MT 128                  // rows per CTA
#define HT 64                   // h-columns per CTA (x4 gates -> 256 N cols)
#define NT 256                  // gate columns per CTA
#define KT 32                   // k per pipeline stage
#define NSTAGE 3
#define PITCH 36                // smem pitch (floats) -> conflict-free LDSM rows
#define A_STAGE_F (128 * PITCH)
#define B_STAGE_F (256 * PITCH)
#define STAGE_F (A_STAGE_F + B_STAGE_F)
#define GP 260                  // gate smem pitch (floats)

// Layer-0 hidden output scratch (static device global: allocation-free)
__device__ float g_h1[(size_t)PB * H_DIM];

__device__ __forceinline__ void cpa16(unsigned saddr, const float* g) {
    asm volatile("cp.async.cg.shared.global [%0], [%1], 16;\n" :: "r"(saddr), "l"(g));
}

// ldmatrix x4: loads 4 8x8 b16 matrices == 4 8x4 tf32 fragments.
__device__ __forceinline__ void ldsm4(uint32_t* r, uint32_t addr) {
    asm volatile("ldmatrix.sync.aligned.m8n8.x4.shared.b16 {%0,%1,%2,%3}, [%4];"
                 : "=r"(r[0]), "=r"(r[1]), "=r"(r[2]), "=r"(r[3]) : "r"(addr));
}

// tf32 mma fed with raw fp32 bits (HW truncates mantissa to tf32)
__device__ __forceinline__ void mma_tf32(float* c, const uint32_t* a,
                                         uint32_t b0, uint32_t b1) {
    asm volatile(
        "mma.sync.aligned.m16n8k8.row.col.f32.tf32.tf32.f32 "
        "{%0,%1,%2,%3}, {%4,%5,%6,%7}, {%8,%9}, {%0,%1,%2,%3};\n"
        : "+f"(c[0]), "+f"(c[1]), "+f"(c[2]), "+f"(c[3])
        : "r"(a[0]), "r"(a[1]), "r"(a[2]), "r"(a[3]), "r"(b0), "r"(b1));
}

__device__ __forceinline__ float tanh_fast(float x) {
    float y;
    asm("tanh.approx.f32 %0, %1;" : "=f"(y) : "f"(x));
    return y;
}
__device__ __forceinline__ float sigmoid_fast(float x) {
    return fmaf(tanh_fast(0.5f * x), 0.5f, 0.5f);
}

// One LSTM layer, fused GEMM (tf32 mma) + cell.
// LAYER==0: gates = x@w_ih0^T (IN=2, scalar in epilogue) + h0[:,0]@w_hh0^T + b
// LAYER==1: gates = h1@w_ih1^T + h0[:,1]@w_hh1^T + b  (K=1024 concat)
template <int LAYER>
__global__ void __launch_bounds__(256, 1)
lstm_layer_kernel(const float* __restrict__ x_in,
                  const float* __restrict__ h0,
                  const float* __restrict__ c0,
                  const float* __restrict__ w_ih,
                  const float* __restrict__ w_hh,
                  const float* __restrict__ b_ih,
                  const float* __restrict__ b_hh,
                  float* __restrict__ d_out) {
    extern __shared__ float smem[];

    const int tid  = threadIdx.x;
    const int warp = tid >> 5;
    const int lane = tid & 31;
    const int wm = warp >> 2;          // 0..1 : 64-row slab
    const int wn = warp & 3;           // 0..3 : 64-col slab
    const int rowW = wm * 64;
    const int colW = wn * 64;

    const int mTile = blockIdx.y;      // 0..127
    const int hTile = blockIdx.x;      // 0..7
    const int rowBase = mTile * MT;
    const int hBase   = hTile * HT;

    const int p0 = rowBase >> 8;       // row = p*256 + b ; 128-row tile stays in one p
    const int b0 = rowBase & 255;

    // A operand base pointers (rows contiguous with stride H_DIM)
    const float* Ab0;
    const float* Ab1;
    if (LAYER == 0) {
        Ab0 = h0 + ((size_t)(p0 * 2 + 0) * B_DIM + b0) * H_DIM;
        Ab1 = Ab0;  // unused
    } else {
        Ab0 = g_h1 + (size_t)rowBase * H_DIM;
        Ab1 = h0 + ((size_t)(p0 * 2 + 1) * B_DIM + b0) * H_DIM;
    }
    const float* Wb0 = (LAYER == 0) ? w_hh : w_ih;
    const float* Wb1 = w_hh;

    const int KTILES = (LAYER == 0) ? 16 : 32;

    const unsigned smem_u = (unsigned)__cvta_generic_to_shared(smem);

    // -------- stage loader: A [128 x KT], B [256(gate-blocked n) x KT] --------
    auto load_stage = [&](int kt, int stage) {
        const float* Ab = (LAYER == 0 || kt < 16) ? Ab0 : Ab1;
        const float* Wb = (LAYER == 0 || kt < 16) ? Wb0 : Wb1;
        const int kk = (kt & 15) * KT;
        const unsigned Asd = smem_u + (unsigned)(stage * STAGE_F) * 4u;
        const unsigned Bsd = Asd + (unsigned)A_STAGE_F * 4u;
#pragma unroll
        for (int i = 0; i < 12; i++) {
            const int c = tid + i * 256;        // 0..3071 : 16B chunks
            if (c < 1024) {                     // A: 128 rows x 8 chunks
                const int r  = c >> 3;
                const int cc = (c & 7) * 4;
                cpa16(Asd + (unsigned)(r * PITCH + cc) * 4u,
                      Ab + (size_t)r * H_DIM + kk + cc);
            } else {                            // B: 256 gate-blocked weight rows
                const int bc = c - 1024;
                const int n  = bc >> 3;
                const int cc = (bc & 7) * 4;
                const int g = n >> 6, j = n & 63;
                cpa16(Bsd + (unsigned)(n * PITCH + cc) * 4u,
                      Wb + (size_t)(g * H_DIM + hBase + j) * H_DIM + kk + cc);
            }
        }
        asm volatile("cp.async.commit_group;\n");
    };

    float acc[4][8][4];
#pragma unroll
    for (int mi = 0; mi < 4; mi++)
#pragma unroll
        for (int nt = 0; nt < 8; nt++)
#pragma unroll
            for (int q = 0; q < 4; q++) acc[mi][nt][q] = 0.0f;

    // -------- per-thread LDSM base offsets (bytes) --------
    const int m8 = lane >> 3;
    const int l8 = lane & 7;
    // A frag (per mi, step 16*PITCH): m0:(r+0,k0) m1:(r+8,k0) m2:(r+0,k0+4) m3:(r+8,k0+4)
    const uint32_t aoff =
        (uint32_t)(((rowW + (m8 & 1) * 8 + l8) * PITCH + (m8 >> 1) * 4) * 4);
    // B frag pair (nt0=2t): m0:b0(nt0) m1:b1(nt0) m2:b0(nt0+1) m3:b1(nt0+1)
    uint32_t boff[4];
#pragma unroll
    for (int t = 0; t < 4; t++)
        boff[t] = (uint32_t)(((colW + (t * 2 + (m8 >> 1)) * 8 + l8) * PITCH
                              + (m8 & 1) * 4) * 4);

    // -------- mainloop: 3-stage cp.async pipeline, one sync per k-tile --------
    load_stage(0, 0);
    load_stage(1, 1);
    asm volatile("cp.async.wait_group 1;\n");   // stage 0 ready
    __syncthreads();

    int s = 0;                                  // = kt % 3
    for (int kt = 0; kt < KTILES; kt++) {
        if (kt + 2 < KTILES) {
            int s2 = s + 2; if (s2 >= 3) s2 -= 3;
            load_stage(kt + 2, s2);
        }

        const uint32_t As = smem_u + (uint32_t)(s * STAGE_F) * 4u;
        const uint32_t Bs = As + (uint32_t)A_STAGE_F * 4u;
#pragma unroll
        for (int k0 = 0; k0 < KT; k0 += 8) {
            uint32_t a[4][4];
#pragma unroll
            for (int mi = 0; mi < 4; mi++)
                ldsm4(a[mi], As + aoff + (uint32_t)(mi * 16 * PITCH * 4) + k0 * 4);
#pragma unroll
            for (int t = 0; t < 4; t++) {
                uint32_t b[4];
                ldsm4(b, Bs + boff[t] + k0 * 4);
#pragma unroll
                for (int mi = 0; mi < 4; mi++) {
                    mma_tf32(acc[mi][2 * t],     a[mi], b[0], b[1]);
                    mma_tf32(acc[mi][2 * t + 1], a[mi], b[2], b[3]);
                }
            }
        }

        if (kt + 1 < KTILES) {
            if (kt + 2 < KTILES) { asm volatile("cp.async.wait_group 1;\n"); }
            else                 { asm volatile("cp.async.wait_group 0;\n"); }
            __syncthreads();
        }
        if (++s == 3) s = 0;
    }
    __syncthreads();   // protect stage smem before G overlay writes

    // -------- epilogue: gates -> smem (overlay pipeline buffers) --------
    float* G = smem;  // [128][GP], col index = gate*64 + j
#pragma unroll
    for (int mi = 0; mi < 4; mi++) {
#pragma unroll
        for (int nt = 0; nt < 8; nt++) {
            const int r  = rowW + mi * 16 + (lane >> 2);
            const int cC = colW + nt * 8 + 2 * (lane & 3);
            G[r * GP + cC]           = acc[mi][nt][0];
            G[r * GP + cC + 1]       = acc[mi][nt][1];
            G[(r + 8) * GP + cC]     = acc[mi][nt][2];
            G[(r + 8) * GP + cC + 1] = acc[mi][nt][3];
        }
    }
    __syncthreads();

    // -------- LSTM cell + stores --------
    const size_t hn_off = (size_t)PB * H_DIM;
    const size_t cn_off = hn_off + (size_t)P_DIM * 2 * B_DIM * H_DIM;

    const int j = tid & 63;           // constant per thread
    const int h = hBase + j;
    const float bi = b_ih[h]             + b_hh[h];
    const float bf = b_ih[H_DIM + h]     + b_hh[H_DIM + h];
    const float bg = b_ih[2 * H_DIM + h] + b_hh[2 * H_DIM + h];
    const float bo = b_ih[3 * H_DIM + h] + b_hh[3 * H_DIM + h];
    float wi0 = 0.f, wi1 = 0.f, wf0 = 0.f, wf1 = 0.f, wg0 = 0.f, wg1 = 0.f, wo0 = 0.f, wo1 = 0.f;
    if (LAYER == 0) {
        wi0 = w_ih[(size_t)h * 2];                    wi1 = w_ih[(size_t)h * 2 + 1];
        wf0 = w_ih[(size_t)(H_DIM + h) * 2];          wf1 = w_ih[(size_t)(H_DIM + h) * 2 + 1];
        wg0 = w_ih[(size_t)(2 * H_DIM + h) * 2];      wg1 = w_ih[(size_t)(2 * H_DIM + h) * 2 + 1];
        wo0 = w_ih[(size_t)(3 * H_DIM + h) * 2];      wo1 = w_ih[(size_t)(3 * H_DIM + h) * 2 + 1];
    }

#pragma unroll 4
    for (int it = 0; it < 32; it++) {             // r covers 0..127 (4 rows/iter)
        const int r   = (tid >> 6) + it * 4;
        const int row = rowBase + r;
        const int p   = row >> 8;
        const int b   = row & 255;

        float gi = G[r * GP + j]       + bi;
        float gf = G[r * GP + 64 + j]  + bf;
        float gg = G[r * GP + 128 + j] + bg;
        float go = G[r * GP + 192 + j] + bo;

        if (LAYER == 0) {
            const float x0 = x_in[(size_t)(b * P_DIM + p) * IN_DIM];
            const float x1 = x_in[(size_t)(b * P_DIM + p) * IN_DIM + 1];
            gi += x0 * wi0 + x1 * wi1;
            gf += x0 * wf0 + x1 * wf1;
            gg += x0 * wg0 + x1 * wg1;
            go += x0 * wo0 + x1 * wo1;
        }

        const float i_s = sigmoid_fast(gi);
        const float f_s = sigmoid_fast(gf);
        const float o_s = sigmoid_fast(go);
        const float g_t = tanh_fast(gg);

        const size_t cidx = (((size_t)p * 2 + LAYER) * B_DIM + b) * H_DIM + h;
        const float c_new = f_s * c0[cidx] + i_s * g_t;
        const float h_new = o_s * tanh_fast(c_new);

        d_out[hn_off + cidx] = h_new;
        d_out[cn_off + cidx] = c_new;
        if (LAYER == 0) {
            g_h1[(size_t)row * H_DIM + h] = h_new;
        } else {
            d_out[((size_t)b * P_DIM + p) * H_DIM + h] = h_new;  // out[b,p,h]
        }
    }
}

extern "C" void kernel_launch(void* const* d_in, const int* in_sizes, int n_in,
                              void* d_out, int out_size) {
    const float* x     = (const float*)d_in[0];   // input_traces [B,P,2]
    const float* h0    = (const float*)d_in[1];   // [P,L,B,H]
    const float* c0    = (const float*)d_in[2];   // [P,L,B,H]
    const float* w_ih0 = (const float*)d_in[3];   // [2048,2]
    const float* w_hh0 = (const float*)d_in[4];   // [2048,512]
    const float* b_ih0 = (const float*)d_in[5];
    const float* b_hh0 = (const float*)d_in[6];
    const float* w_ih1 = (const float*)d_in[7];   // [2048,512]
    const float* w_hh1 = (const float*)d_in[8];   // [2048,512]
    const float* b_ih1 = (const float*)d_in[9];
    const float* b_hh1 = (const float*)d_in[10];
    float* out = (float*)d_out;

    const int smem_bytes = NSTAGE * STAGE_F * 4;  // 165888 B
    cudaFuncSetAttribute(lstm_layer_kernel<0>,
                         cudaFuncAttributeMaxDynamicSharedMemorySize, smem_bytes);
    cudaFuncSetAttribute(lstm_layer_kernel<1>,
                         cudaFuncAttributeMaxDynamicSharedMemorySize, smem_bytes);

    dim3 grid(H_DIM / HT, PB / MT);               // (8, 128)
    lstm_layer_kernel<0><<<grid, 256, smem_bytes>>>(x, h0, c0, w_ih0, w_hh0,
                                                    b_ih0, b_hh0, out);
    lstm_layer_kernel<1><<<grid, 256, smem_bytes>>>(nullptr, h0, c0, w_ih1, w_hh1,
                                                    b_ih1, b_hh1, out);
}

// round 12
// speedup vs baseline: 1.8945x; 1.8945x over previous
#include <cuda_runtime.h>
#include <cuda_fp16.h>
#include <cstdint>

// Problem constants
#define P_DIM 64
#define B_DIM 256
#define H_DIM 512
#define IN_DIM 2
#define PB (P_DIM * B_DIM)      // 16384 fused batch rows

// Tiling (R9 geometry, fp16 operands)
#define MT 128                  // rows per CTA
#define HT 32                   // h-columns per CTA (x4 gates -> 128 N cols)
#define KTH 64                  // k (halves) per pipeline stage = 128B rows
#define NSTAGE 3
#define PITCH_B 144             // bytes per smem row (72 halves) -> conflict-free LDSM
#define A_STAGE_B (128 * PITCH_B)
#define STAGE_B (2 * A_STAGE_B)            // A + B tiles: 36864 B
#define GP 132                  // gate smem pitch (floats)

// fp16 scratch (device globals: allocation-free)
__device__ __half g_h0h[(size_t)P_DIM * 2 * B_DIM * H_DIM];   // h0 converted
__device__ __half g_h1h[(size_t)PB * H_DIM];                  // layer-0 output
__device__ __half g_w16[3][2048 * 512];                       // w_hh0, w_ih1, w_hh1

__device__ __forceinline__ void cpa16(unsigned saddr, const __half* g) {
    asm volatile("cp.async.cg.shared.global [%0], [%1], 16;\n" :: "r"(saddr), "l"(g));
}

// ldmatrix x4: 4 8x8 b16 matrices
__device__ __forceinline__ void ldsm4(uint32_t* r, uint32_t addr) {
    asm volatile("ldmatrix.sync.aligned.m8n8.x4.shared.b16 {%0,%1,%2,%3}, [%4];"
                 : "=r"(r[0]), "=r"(r[1]), "=r"(r[2]), "=r"(r[3]) : "r"(addr));
}

__device__ __forceinline__ void mma_f16(float* c, const uint32_t* a,
                                        uint32_t b0, uint32_t b1) {
    asm volatile(
        "mma.sync.aligned.m16n8k16.row.col.f32.f16.f16.f32 "
        "{%0,%1,%2,%3}, {%4,%5,%6,%7}, {%8,%9}, {%0,%1,%2,%3};\n"
        : "+f"(c[0]), "+f"(c[1]), "+f"(c[2]), "+f"(c[3])
        : "r"(a[0]), "r"(a[1]), "r"(a[2]), "r"(a[3]), "r"(b0), "r"(b1));
}

__device__ __forceinline__ float tanh_fast(float x) {
    float y;
    asm("tanh.approx.f32 %0, %1;" : "=f"(y) : "f"(x));
    return y;
}
__device__ __forceinline__ float sigmoid_fast(float x) {
    return fmaf(tanh_fast(0.5f * x), 0.5f, 0.5f);
}

// -------- conversion prologue kernels --------
__global__ void cvt_h0_kernel(const float4* __restrict__ src) {
    const size_t n4 = (size_t)P_DIM * 2 * B_DIM * H_DIM / 4;
    __half2* dst = (__half2*)g_h0h;
    for (size_t i = (size_t)blockIdx.x * blockDim.x + threadIdx.x; i < n4;
         i += (size_t)gridDim.x * blockDim.x) {
        float4 v = src[i];
        dst[2 * i]     = __floats2half2_rn(v.x, v.y);
        dst[2 * i + 1] = __floats2half2_rn(v.z, v.w);
    }
}

__global__ void cvt_w_kernel(const float4* __restrict__ w0,
                             const float4* __restrict__ w1,
                             const float4* __restrict__ w2) {
    const size_t n4 = (size_t)2048 * 512 / 4;   // per array
    for (size_t i = (size_t)blockIdx.x * blockDim.x + threadIdx.x; i < 3 * n4;
         i += (size_t)gridDim.x * blockDim.x) {
        const int sel = (int)(i / n4);
        const size_t j = i - (size_t)sel * n4;
        const float4* s = (sel == 0) ? w0 : (sel == 1) ? w1 : w2;
        float4 v = s[j];
        __half2* dst = (__half2*)g_w16[sel];
        dst[2 * j]     = __floats2half2_rn(v.x, v.y);
        dst[2 * j + 1] = __floats2half2_rn(v.z, v.w);
    }
}

// One LSTM layer, fused GEMM (fp16 mma, fp32 accum) + cell.
// LAYER==0: gates = x@w_ih0^T (IN=2, scalar epilogue) + h0[:,0]@w_hh0^T + b
// LAYER==1: gates = h1@w_ih1^T + h0[:,1]@w_hh1^T + b  (K=1024 concat)
template <int LAYER>
__global__ void __launch_bounds__(256, 2)
lstm_layer_kernel(const float* __restrict__ x_in,
                  const float* __restrict__ c0,
                  const float* __restrict__ w_ih0,
                  const float* __restrict__ b_ih,
                  const float* __restrict__ b_hh,
                  float* __restrict__ d_out) {
    extern __shared__ float smem[];

    const int tid  = threadIdx.x;
    const int warp = tid >> 5;
    const int lane = tid & 31;
    const int wm = warp >> 1;          // 0..3 : 32-row slab
    const int wn = warp & 1;           // 0..1 : 64-col half
    const int rowW = wm * 32;
    const int colW = wn * 64;

    const int mTile = blockIdx.y;      // 0..127
    const int hTile = blockIdx.x;      // 0..15
    const int rowBase = mTile * MT;
    const int hBase   = hTile * HT;

    const int p0 = rowBase >> 8;       // row = p*256 + b
    const int b0 = rowBase & 255;

    // fp16 A operand base pointers (rows contiguous with stride H_DIM)
    const __half* Ab0 = (LAYER == 0)
        ? g_h0h + ((size_t)(p0 * 2 + 0) * B_DIM + b0) * H_DIM
        : g_h1h + (size_t)rowBase * H_DIM;
    const __half* Ab1 = g_h0h + ((size_t)(p0 * 2 + 1) * B_DIM + b0) * H_DIM;
    const __half* Wb0 = (LAYER == 0) ? g_w16[0] : g_w16[1];
    const __half* Wb1 = g_w16[2];

    const int KTILES = (LAYER == 0) ? 8 : 16;   // K/64

    const unsigned smem_u = (unsigned)__cvta_generic_to_shared(smem);

    // -------- stage loader: A [128 x 64h], B [128(gate-blocked n) x 64h] --------
    auto load_stage = [&](int kt, int stage) {
        const __half* Ab = (LAYER == 0 || kt < 8) ? Ab0 : Ab1;
        const __half* Wb = (LAYER == 0 || kt < 8) ? Wb0 : Wb1;
        const int kk = (kt & 7) * KTH;
        const unsigned Asd = smem_u + (unsigned)(stage * STAGE_B);
        const unsigned Bsd = Asd + (unsigned)A_STAGE_B;
#pragma unroll
        for (int i = 0; i < 4; i++) {
            const int c  = tid + i * 256;       // 0..1023 : 16B chunks
            const int r  = c >> 3;              // 0..127
            const int cc = c & 7;               // chunk within row
            cpa16(Asd + (unsigned)(r * PITCH_B + cc * 16),
                  Ab + (size_t)r * H_DIM + kk + cc * 8);
            const int g = r >> 5, j = r & 31;   // gate-blocked weight row
            cpa16(Bsd + (unsigned)(r * PITCH_B + cc * 16),
                  Wb + (size_t)(g * H_DIM + hBase + j) * H_DIM + kk + cc * 8);
        }
        asm volatile("cp.async.commit_group;\n");
    };

    float acc[2][8][4];
#pragma unroll
    for (int mi = 0; mi < 2; mi++)
#pragma unroll
        for (int nt = 0; nt < 8; nt++)
#pragma unroll
            for (int q = 0; q < 4; q++) acc[mi][nt][q] = 0.0f;

    // -------- per-thread LDSM base offsets (bytes) --------
    const int m8 = lane >> 3;
    const int l8 = lane & 7;
    // A frag: m0:(r+0,k0-7) m1:(r+8,k0-7) m2:(r+0,k8-15) m3:(r+8,k8-15)
    const uint32_t aoff =
        (uint32_t)((rowW + (m8 & 1) * 8 + l8) * PITCH_B + (m8 >> 1) * 16);
    // B frag pair (nt0=2t): m0:b0(nt0) m1:b1(nt0) m2:b0(nt0+1) m3:b1(nt0+1)
    uint32_t boff[4];
#pragma unroll
    for (int t = 0; t < 4; t++)
        boff[t] = (uint32_t)((colW + (t * 2 + (m8 >> 1)) * 8 + l8) * PITCH_B
                             + (m8 & 1) * 16);

    // -------- mainloop: 3-stage cp.async pipeline, one sync per k-tile --------
    load_stage(0, 0);
    load_stage(1, 1);
    asm volatile("cp.async.wait_group 1;\n");
    __syncthreads();

    int s = 0;
    for (int kt = 0; kt < KTILES; kt++) {
        if (kt + 2 < KTILES) {
            int s2 = s + 2; if (s2 >= 3) s2 -= 3;
            load_stage(kt + 2, s2);
        }

        const uint32_t As = smem_u + (uint32_t)(s * STAGE_B);
        const uint32_t Bs = As + (uint32_t)A_STAGE_B;
#pragma unroll
        for (int k0 = 0; k0 < 4; k0++) {        // 4 x K=16 steps (32B each)
            uint32_t a0[4], a1[4];
            ldsm4(a0, As + aoff + k0 * 32);
            ldsm4(a1, As + aoff + (uint32_t)(16 * PITCH_B) + k0 * 32);
#pragma unroll
            for (int t = 0; t < 4; t++) {
                uint32_t b[4];
                ldsm4(b, Bs + boff[t] + k0 * 32);
                mma_f16(acc[0][2 * t],     a0, b[0], b[1]);
                mma_f16(acc[1][2 * t],     a1, b[0], b[1]);
                mma_f16(acc[0][2 * t + 1], a0, b[2], b[3]);
                mma_f16(acc[1][2 * t + 1], a1, b[2], b[3]);
            }
        }

        if (kt + 1 < KTILES) {
            if (kt + 2 < KTILES) { asm volatile("cp.async.wait_group 1;\n"); }
            else                 { asm volatile("cp.async.wait_group 0;\n"); }
            __syncthreads();
        }
        if (++s == 3) s = 0;
    }
    __syncthreads();   // protect stage smem before G overlay writes

    // -------- epilogue: gates -> smem (overlay pipeline buffers) --------
    float* G = smem;  // [128][GP], col index = gate*32 + j
#pragma unroll
    for (int mi = 0; mi < 2; mi++) {
#pragma unroll
        for (int nt = 0; nt < 8; nt++) {
            const int r  = rowW + mi * 16 + (lane >> 2);
            const int cC = colW + nt * 8 + 2 * (lane & 3);
            G[r * GP + cC]           = acc[mi][nt][0];
            G[r * GP + cC + 1]       = acc[mi][nt][1];
            G[(r + 8) * GP + cC]     = acc[mi][nt][2];
            G[(r + 8) * GP + cC + 1] = acc[mi][nt][3];
        }
    }
    __syncthreads();

    // -------- LSTM cell + stores --------
    const size_t hn_off = (size_t)PB * H_DIM;
    const size_t cn_off = hn_off + (size_t)P_DIM * 2 * B_DIM * H_DIM;

    const int j = tid & 31;
    const int h = hBase + j;
    const float bi = b_ih[h]             + b_hh[h];
    const float bf = b_ih[H_DIM + h]     + b_hh[H_DIM + h];
    const float bg = b_ih[2 * H_DIM + h] + b_hh[2 * H_DIM + h];
    const float bo = b_ih[3 * H_DIM + h] + b_hh[3 * H_DIM + h];
    float wi0 = 0.f, wi1 = 0.f, wf0 = 0.f, wf1 = 0.f, wg0 = 0.f, wg1 = 0.f, wo0 = 0.f, wo1 = 0.f;
    if (LAYER == 0) {
        wi0 = w_ih0[(size_t)h * 2];                    wi1 = w_ih0[(size_t)h * 2 + 1];
        wf0 = w_ih0[(size_t)(H_DIM + h) * 2];          wf1 = w_ih0[(size_t)(H_DIM + h) * 2 + 1];
        wg0 = w_ih0[(size_t)(2 * H_DIM + h) * 2];      wg1 = w_ih0[(size_t)(2 * H_DIM + h) * 2 + 1];
        wo0 = w_ih0[(size_t)(3 * H_DIM + h) * 2];      wo1 = w_ih0[(size_t)(3 * H_DIM + h) * 2 + 1];
    }

#pragma unroll 4
    for (int it = 0; it < 16; it++) {             // r covers 0..127
        const int r   = (tid >> 5) + it * 8;
        const int row = rowBase + r;
        const int p   = row >> 8;
        const int b   = row & 255;

        float gi = G[r * GP + j]      + bi;
        float gf = G[r * GP + 32 + j] + bf;
        float gg = G[r * GP + 64 + j] + bg;
        float go = G[r * GP + 96 + j] + bo;

        if (LAYER == 0) {
            const float x0 = x_in[(size_t)(b * P_DIM + p) * IN_DIM];
            const float x1 = x_in[(size_t)(b * P_DIM + p) * IN_DIM + 1];
            gi += x0 * wi0 + x1 * wi1;
            gf += x0 * wf0 + x1 * wf1;
            gg += x0 * wg0 + x1 * wg1;
            go += x0 * wo0 + x1 * wo1;
        }

        const float i_s = sigmoid_fast(gi);
        const float f_s = sigmoid_fast(gf);
        const float o_s = sigmoid_fast(go);
        const float g_t = tanh_fast(gg);

        const size_t cidx = (((size_t)p * 2 + LAYER) * B_DIM + b) * H_DIM + h;
        const float c_new = f_s * c0[cidx] + i_s * g_t;
        const float h_new = o_s * tanh_fast(c_new);

        d_out[hn_off + cidx] = h_new;
        d_out[cn_off + cidx] = c_new;
        if (LAYER == 0) {
            g_h1h[(size_t)row * H_DIM + h] = __float2half_rn(h_new);
        } else {
            d_out[((size_t)b * P_DIM + p) * H_DIM + h] = h_new;  // out[b,p,h]
        }
    }
}

extern "C" void kernel_launch(void* const* d_in, const int* in_sizes, int n_in,
                              void* d_out, int out_size) {
    const float* x     = (const float*)d_in[0];   // input_traces [B,P,2]
    const float* h0    = (const float*)d_in[1];   // [P,L,B,H]
    const float* c0    = (const float*)d_in[2];   // [P,L,B,H]
    const float* w_ih0 = (const float*)d_in[3];   // [2048,2]
    const float* w_hh0 = (const float*)d_in[4];   // [2048,512]
    const float* b_ih0 = (const float*)d_in[5];
    const float* b_hh0 = (const float*)d_in[6];
    const float* w_ih1 = (const float*)d_in[7];   // [2048,512]
    const float* w_hh1 = (const float*)d_in[8];   // [2048,512]
    const float* b_ih1 = (const float*)d_in[9];
    const float* b_hh1 = (const float*)d_in[10];
    float* out = (float*)d_out;

    // prologue: fp32 -> fp16 conversions
    cvt_h0_kernel<<<2048, 256>>>((const float4*)h0);
    cvt_w_kernel<<<768, 256>>>((const float4*)w_hh0, (const float4*)w_ih1,
                               (const float4*)w_hh1);

    const int smem_bytes = NSTAGE * STAGE_B;      // 110592 B
    cudaFuncSetAttribute(lstm_layer_kernel<0>,
                         cudaFuncAttributeMaxDynamicSharedMemorySize, smem_bytes);
    cudaFuncSetAttribute(lstm_layer_kernel<1>,
                         cudaFuncAttributeMaxDynamicSharedMemorySize, smem_bytes);

    dim3 grid(H_DIM / HT, PB / MT);               // (16, 128)
    lstm_layer_kernel<0><<<grid, 256, smem_bytes>>>(x, c0, w_ih0, b_ih0, b_hh0, out);
    lstm_layer_kernel<1><<<grid, 256, smem_bytes>>>(nullptr, c0, nullptr,
                                                    b_ih1, b_hh1, out);
}

// round 13
// speedup vs baseline: 1.9214x; 1.0142x over previous
#include <cuda_runtime.h>
#include <cuda_fp16.h>
#include <cstdint>

// Problem constants
#define P_DIM 64
#define B_DIM 256
#define H_DIM 512
#define IN_DIM 2
#define PB (P_DIM * B_DIM)      // 16384 fused batch rows

// Tiling (R12 geometry, fp16 operands)
#define MT 128                  // rows per CTA
#define HT 32                   // h-columns per CTA (x4 gates -> 128 N cols)
#define KTH 64                  // k (halves) per pipeline stage = 128B rows
#define NSTAGE 3
#define PITCH_B 144             // bytes per smem row (72 halves) -> conflict-free LDSM
#define A_STAGE_B (128 * PITCH_B)
#define STAGE_B (2 * A_STAGE_B)            // A + B tiles: 36864 B
#define GP 132                  // gate smem pitch (floats)

// fp16 scratch (device globals: allocation-free)
__device__ __half g_h0h[(size_t)P_DIM * 2 * B_DIM * H_DIM];   // h0 converted
__device__ __half g_h1h[(size_t)PB * H_DIM];                  // layer-0 output
__device__ __half g_w16[3][2048 * 512];                       // w_hh0, w_ih1, w_hh1

__device__ __forceinline__ void cpa16(unsigned saddr, const __half* g) {
    asm volatile("cp.async.cg.shared.global [%0], [%1], 16;\n" :: "r"(saddr), "l"(g));
}

// ldmatrix x4: 4 8x8 b16 matrices
__device__ __forceinline__ void ldsm4(uint32_t* r, uint32_t addr) {
    asm volatile("ldmatrix.sync.aligned.m8n8.x4.shared.b16 {%0,%1,%2,%3}, [%4];"
                 : "=r"(r[0]), "=r"(r[1]), "=r"(r[2]), "=r"(r[3]) : "r"(addr));
}

__device__ __forceinline__ void mma_f16(float* c, const uint32_t* a,
                                        uint32_t b0, uint32_t b1) {
    asm volatile(
        "mma.sync.aligned.m16n8k16.row.col.f32.f16.f16.f32 "
        "{%0,%1,%2,%3}, {%4,%5,%6,%7}, {%8,%9}, {%0,%1,%2,%3};\n"
        : "+f"(c[0]), "+f"(c[1]), "+f"(c[2]), "+f"(c[3])
        : "r"(a[0]), "r"(a[1]), "r"(a[2]), "r"(a[3]), "r"(b0), "r"(b1));
}

__device__ __forceinline__ float tanh_fast(float x) {
    float y;
    asm("tanh.approx.f32 %0, %1;" : "=f"(y) : "f"(x));
    return y;
}
__device__ __forceinline__ float sigmoid_fast(float x) {
    return fmaf(tanh_fast(0.5f * x), 0.5f, 0.5f);
}

// -------- merged conversion prologue: h0 + 3 weight matrices -> fp16 --------
__global__ void cvt_all_kernel(const float4* __restrict__ h0,
                               const float4* __restrict__ w0,
                               const float4* __restrict__ w1,
                               const float4* __restrict__ w2) {
    const size_t nh = (size_t)P_DIM * 2 * B_DIM * H_DIM / 4;   // 4194304
    const size_t nw = (size_t)2048 * 512 / 4;                  // 262144
    const size_t total = nh + 3 * nw;
    for (size_t i = (size_t)blockIdx.x * blockDim.x + threadIdx.x; i < total;
         i += (size_t)gridDim.x * blockDim.x) {
        const float4* src; __half2* dst; size_t j;
        if (i < nh) {
            src = h0; dst = (__half2*)g_h0h; j = i;
        } else {
            const size_t k = i - nh;
            const int sel = (int)(k / nw);
            j = k - (size_t)sel * nw;
            src = (sel == 0) ? w0 : (sel == 1) ? w1 : w2;
            dst = (__half2*)g_w16[sel];
        }
        float4 v = src[j];
        dst[2 * j]     = __floats2half2_rn(v.x, v.y);
        dst[2 * j + 1] = __floats2half2_rn(v.z, v.w);
    }
}

// One LSTM layer, fused GEMM (fp16 mma, fp32 accum) + cell.
// LAYER==0: gates = x@w_ih0^T (IN=2, scalar epilogue) + h0[:,0]@w_hh0^T + b
// LAYER==1: gates = h1@w_ih1^T + h0[:,1]@w_hh1^T + b  (K=1024 concat)
template <int LAYER>
__global__ void __launch_bounds__(256, 2)
lstm_layer_kernel(const float* __restrict__ x_in,
                  const float* __restrict__ c0,
                  const float* __restrict__ w_ih0,
                  const float* __restrict__ b_ih,
                  const float* __restrict__ b_hh,
                  float* __restrict__ d_out) {
    extern __shared__ float smem[];

    const int tid  = threadIdx.x;
    const int warp = tid >> 5;
    const int lane = tid & 31;
    const int wm = warp >> 1;          // 0..3 : 32-row slab
    const int wn = warp & 1;           // 0..1 : 64-col half
    const int rowW = wm * 32;
    const int colW = wn * 64;

    const int mTile = blockIdx.y;      // 0..127
    const int hTile = blockIdx.x;      // 0..15
    const int rowBase = mTile * MT;
    const int hBase   = hTile * HT;

    const int p0 = rowBase >> 8;       // row = p*256 + b
    const int b0 = rowBase & 255;

    // fp16 A operand base pointers (rows contiguous with stride H_DIM)
    const __half* Ab0 = (LAYER == 0)
        ? g_h0h + ((size_t)(p0 * 2 + 0) * B_DIM + b0) * H_DIM
        : g_h1h + (size_t)rowBase * H_DIM;
    const __half* Ab1 = g_h0h + ((size_t)(p0 * 2 + 1) * B_DIM + b0) * H_DIM;
    const __half* Wb0 = (LAYER == 0) ? g_w16[0] : g_w16[1];
    const __half* Wb1 = g_w16[2];

    const int KTILES = (LAYER == 0) ? 8 : 16;   // K/64

    const unsigned smem_u = (unsigned)__cvta_generic_to_shared(smem);

    // -------- stage loader: A [128 x 64h], B [128(gate-blocked n) x 64h] --------
    auto load_stage = [&](int kt, int stage) {
        const __half* Ab = (LAYER == 0 || kt < 8) ? Ab0 : Ab1;
        const __half* Wb = (LAYER == 0 || kt < 8) ? Wb0 : Wb1;
        const int kk = (kt & 7) * KTH;
        const unsigned Asd = smem_u + (unsigned)(stage * STAGE_B);
        const unsigned Bsd = Asd + (unsigned)A_STAGE_B;
#pragma unroll
        for (int i = 0; i < 4; i++) {
            const int c  = tid + i * 256;       // 0..1023 : 16B chunks
            const int r  = c >> 3;              // 0..127
            const int cc = c & 7;               // chunk within row
            cpa16(Asd + (unsigned)(r * PITCH_B + cc * 16),
                  Ab + (size_t)r * H_DIM + kk + cc * 8);
            const int g = r >> 5, j = r & 31;   // gate-blocked weight row
            cpa16(Bsd + (unsigned)(r * PITCH_B + cc * 16),
                  Wb + (size_t)(g * H_DIM + hBase + j) * H_DIM + kk + cc * 8);
        }
        asm volatile("cp.async.commit_group;\n");
    };

    float acc[2][8][4];
#pragma unroll
    for (int mi = 0; mi < 2; mi++)
#pragma unroll
        for (int nt = 0; nt < 8; nt++)
#pragma unroll
            for (int q = 0; q < 4; q++) acc[mi][nt][q] = 0.0f;

    // -------- per-thread LDSM base offsets (bytes) --------
    const int m8 = lane >> 3;
    const int l8 = lane & 7;
    // A frag: m0:(r+0,k0-7) m1:(r+8,k0-7) m2:(r+0,k8-15) m3:(r+8,k8-15)
    const uint32_t aoff =
        (uint32_t)((rowW + (m8 & 1) * 8 + l8) * PITCH_B + (m8 >> 1) * 16);
    // B frag pair (nt0=2t): m0:b0(nt0) m1:b1(nt0) m2:b0(nt0+1) m3:b1(nt0+1)
    uint32_t boff[4];
#pragma unroll
    for (int t = 0; t < 4; t++)
        boff[t] = (uint32_t)((colW + (t * 2 + (m8 >> 1)) * 8 + l8) * PITCH_B
                             + (m8 & 1) * 16);

    // -------- mainloop: 3-stage cp.async pipeline + register frag pipelining --------
    load_stage(0, 0);
    load_stage(1, 1);
    asm volatile("cp.async.wait_group 1;\n");
    __syncthreads();

    int s = 0;
    for (int kt = 0; kt < KTILES; kt++) {
        const uint32_t As = smem_u + (uint32_t)(s * STAGE_B);
        const uint32_t Bs = As + (uint32_t)A_STAGE_B;

        // initial fragment loads for this k-tile (only exposed chain per tile)
        uint32_t afr[2][8], bfr[2][4];
        ldsm4(&afr[0][0], As + aoff);
        ldsm4(&afr[0][4], As + aoff + (uint32_t)(16 * PITCH_B));
        ldsm4(bfr[0], Bs + boff[0]);

        if (kt + 2 < KTILES) {
            int s2 = s + 2; if (s2 >= 3) s2 -= 3;
            load_stage(kt + 2, s2);
        }

        int cur = 0;
#pragma unroll
        for (int k0 = 0; k0 < 4; k0++) {
#pragma unroll
            for (int t = 0; t < 4; t++) {
                // prefetch one step ahead (reg double-buffering)
                if (t < 3) {
                    ldsm4(bfr[(t + 1) & 1], Bs + boff[t + 1] + k0 * 32);
                } else if (k0 < 3) {
                    ldsm4(&afr[cur ^ 1][0], As + aoff + (k0 + 1) * 32);
                    ldsm4(&afr[cur ^ 1][4],
                          As + aoff + (uint32_t)(16 * PITCH_B) + (k0 + 1) * 32);
                    ldsm4(bfr[0], Bs + boff[0] + (k0 + 1) * 32);
                }
                const uint32_t* b = bfr[t & 1];
                mma_f16(acc[0][2 * t],     &afr[cur][0], b[0], b[1]);
                mma_f16(acc[1][2 * t],     &afr[cur][4], b[0], b[1]);
                mma_f16(acc[0][2 * t + 1], &afr[cur][0], b[2], b[3]);
                mma_f16(acc[1][2 * t + 1], &afr[cur][4], b[2], b[3]);
            }
            cur ^= 1;
        }

        if (kt + 1 < KTILES) {
            if (kt + 2 < KTILES) { asm volatile("cp.async.wait_group 1;\n"); }
            else                 { asm volatile("cp.async.wait_group 0;\n"); }
            __syncthreads();
        }
        if (++s == 3) s = 0;
    }
    __syncthreads();   // protect stage smem before G overlay writes

    // -------- epilogue: gates -> smem (overlay pipeline buffers) --------
    float* G = smem;  // [128][GP], col index = gate*32 + j
#pragma unroll
    for (int mi = 0; mi < 2; mi++) {
#pragma unroll
        for (int nt = 0; nt < 8; nt++) {
            const int r  = rowW + mi * 16 + (lane >> 2);
            const int cC = colW + nt * 8 + 2 * (lane & 3);
            G[r * GP + cC]           = acc[mi][nt][0];
            G[r * GP + cC + 1]       = acc[mi][nt][1];
            G[(r + 8) * GP + cC]     = acc[mi][nt][2];
            G[(r + 8) * GP + cC + 1] = acc[mi][nt][3];
        }
    }
    __syncthreads();

    // -------- LSTM cell + stores --------
    const size_t hn_off = (size_t)PB * H_DIM;
    const size_t cn_off = hn_off + (size_t)P_DIM * 2 * B_DIM * H_DIM;

    const int j = tid & 31;
    const int h = hBase + j;
    const float bi = b_ih[h]             + b_hh[h];
    const float bf = b_ih[H_DIM + h]     + b_hh[H_DIM + h];
    const float bg = b_ih[2 * H_DIM + h] + b_hh[2 * H_DIM + h];
    const float bo = b_ih[3 * H_DIM + h] + b_hh[3 * H_DIM + h];
    float wi0 = 0.f, wi1 = 0.f, wf0 = 0.f, wf1 = 0.f, wg0 = 0.f, wg1 = 0.f, wo0 = 0.f, wo1 = 0.f;
    if (LAYER == 0) {
        wi0 = w_ih0[(size_t)h * 2];                    wi1 = w_ih0[(size_t)h * 2 + 1];
        wf0 = w_ih0[(size_t)(H_DIM + h) * 2];          wf1 = w_ih0[(size_t)(H_DIM + h) * 2 + 1];
        wg0 = w_ih0[(size_t)(2 * H_DIM + h) * 2];      wg1 = w_ih0[(size_t)(2 * H_DIM + h) * 2 + 1];
        wo0 = w_ih0[(size_t)(3 * H_DIM + h) * 2];      wo1 = w_ih0[(size_t)(3 * H_DIM + h) * 2 + 1];
    }

#pragma unroll 4
    for (int it = 0; it < 16; it++) {             // r covers 0..127
        const int r   = (tid >> 5) + it * 8;
        const int row = rowBase + r;
        const int p   = row >> 8;
        const int b   = row & 255;

        float gi = G[r * GP + j]      + bi;
        float gf = G[r * GP + 32 + j] + bf;
        float gg = G[r * GP + 64 + j] + bg;
        float go = G[r * GP + 96 + j] + bo;

        if (LAYER == 0) {
            const float x0 = x_in[(size_t)(b * P_DIM + p) * IN_DIM];
            const float x1 = x_in[(size_t)(b * P_DIM + p) * IN_DIM + 1];
            gi += x0 * wi0 + x1 * wi1;
            gf += x0 * wf0 + x1 * wf1;
            gg += x0 * wg0 + x1 * wg1;
            go += x0 * wo0 + x1 * wo1;
        }

        const float i_s = sigmoid_fast(gi);
        const float f_s = sigmoid_fast(gf);
        const float o_s = sigmoid_fast(go);
        const float g_t = tanh_fast(gg);

        const size_t cidx = (((size_t)p * 2 + LAYER) * B_DIM + b) * H_DIM + h;
        const float c_new = f_s * c0[cidx] + i_s * g_t;
        const float h_new = o_s * tanh_fast(c_new);

        d_out[hn_off + cidx] = h_new;
        d_out[cn_off + cidx] = c_new;
        if (LAYER == 0) {
            g_h1h[(size_t)row * H_DIM + h] = __float2half_rn(h_new);
        } else {
            d_out[((size_t)b * P_DIM + p) * H_DIM + h] = h_new;  // out[b,p,h]
        }
    }
}

extern "C" void kernel_launch(void* const* d_in, const int* in_sizes, int n_in,
                              void* d_out, int out_size) {
    const float* x     = (const float*)d_in[0];   // input_traces [B,P,2]
    const float* h0    = (const float*)d_in[1];   // [P,L,B,H]
    const float* c0    = (const float*)d_in[2];   // [P,L,B,H]
    const float* w_ih0 = (const float*)d_in[3];   // [2048,2]
    const float* w_hh0 = (const float*)d_in[4];   // [2048,512]
    const float* b_ih0 = (const float*)d_in[5];
    const float* b_hh0 = (const float*)d_in[6];
    const float* w_ih1 = (const float*)d_in[7];   // [2048,512]
    const float* w_hh1 = (const float*)d_in[8];   // [2048,512]
    const float* b_ih1 = (const float*)d_in[9];
    const float* b_hh1 = (const float*)d_in[10];
    float* out = (float*)d_out;

    // prologue: fp32 -> fp16 conversions (single merged kernel)
    cvt_all_kernel<<<4096, 256>>>((const float4*)h0, (const float4*)w_hh0,
                                  (const float4*)w_ih1, (const float4*)w_hh1);

    const int smem_bytes = NSTAGE * STAGE_B;      // 110592 B
    cudaFuncSetAttribute(lstm_layer_kernel<0>,
                         cudaFuncAttributeMaxDynamicSharedMemorySize, smem_bytes);
    cudaFuncSetAttribute(lstm_layer_kernel<1>,
                         cudaFuncAttributeMaxDynamicSharedMemorySize, smem_bytes);

    dim3 grid(H_DIM / HT, PB / MT);               // (16, 128)
    lstm_layer_kernel<0><<<grid, 256, smem_bytes>>>(x, c0, w_ih0, b_ih0, b_hh0, out);
    lstm_layer_kernel<1><<<grid, 256, smem_bytes>>>(nullptr, c0, nullptr,
                                                    b_ih1, b_hh1, out);
}

// round 14
// speedup vs baseline: 2.2426x; 1.1672x over previous
#include <cuda_runtime.h>
#include <cuda_fp16.h>
#include <cstdint>

// Problem constants
#define P_DIM 64
#define B_DIM 256
#define H_DIM 512
#define IN_DIM 2
#define PB (P_DIM * B_DIM)      // 16384 fused batch rows

// Tiling (fp16 operands, mbarrier free-running pipeline)
#define MT 128                  // rows per CTA
#define HT 32                   // h-columns per CTA (x4 gates -> 128 N cols)
#define KTH 64                  // k (halves) per pipeline stage = 128B rows
#define NSTAGE 3
#define PITCH_B 144             // bytes per smem row (72 halves) -> conflict-free LDSM
#define A_STAGE_B (128 * PITCH_B)
#define STAGE_B (2 * A_STAGE_B)            // A + B tiles: 36864 B
#define OFF_FULL  (NSTAGE * STAGE_B)       // 110592
#define OFF_EMPTY (OFF_FULL + NSTAGE * 8)
#define SMEM_TOTAL (OFF_EMPTY + NSTAGE * 8 + 16)
#define GP 132                  // gate smem pitch (floats)

// fp16 scratch (device globals: allocation-free)
__device__ __half g_h0h[(size_t)P_DIM * 2 * B_DIM * H_DIM];   // h0 converted
__device__ __half g_h1h[(size_t)PB * H_DIM];                  // layer-0 output
__device__ __half g_w16[3][2048 * 512];                       // w_hh0, w_ih1, w_hh1

__device__ __forceinline__ void cpa16(unsigned saddr, const __half* g) {
    asm volatile("cp.async.cg.shared.global [%0], [%1], 16;\n" :: "r"(saddr), "l"(g));
}
__device__ __forceinline__ void mbar_init(uint32_t a, uint32_t n) {
    asm volatile("mbarrier.init.shared.b64 [%0], %1;" :: "r"(a), "r"(n) : "memory");
}
__device__ __forceinline__ void mbar_wait(uint32_t a, uint32_t par) {
    asm volatile(
        "{\n\t.reg .pred P;\n"
        "WL%=:\n\t"
        "mbarrier.try_wait.parity.shared.b64 P, [%0], %1;\n\t"
        "@!P bra WL%=;\n\t"
        "}" :: "r"(a), "r"(par) : "memory");
}
__device__ __forceinline__ void mbar_arrive(uint32_t a) {
    asm volatile("mbarrier.arrive.shared.b64 _, [%0];" :: "r"(a) : "memory");
}
__device__ __forceinline__ void cpasync_arrive(uint32_t a) {
    asm volatile("cp.async.mbarrier.arrive.noinc.shared.b64 [%0];" :: "r"(a) : "memory");
}

// ldmatrix x4: 4 8x8 b16 matrices
__device__ __forceinline__ void ldsm4(uint32_t* r, uint32_t addr) {
    asm volatile("ldmatrix.sync.aligned.m8n8.x4.shared.b16 {%0,%1,%2,%3}, [%4];"
                 : "=r"(r[0]), "=r"(r[1]), "=r"(r[2]), "=r"(r[3]) : "r"(addr));
}

__device__ __forceinline__ void mma_f16(float* c, const uint32_t* a,
                                        uint32_t b0, uint32_t b1) {
    asm volatile(
        "mma.sync.aligned.m16n8k16.row.col.f32.f16.f16.f32 "
        "{%0,%1,%2,%3}, {%4,%5,%6,%7}, {%8,%9}, {%0,%1,%2,%3};\n"
        : "+f"(c[0]), "+f"(c[1]), "+f"(c[2]), "+f"(c[3])
        : "r"(a[0]), "r"(a[1]), "r"(a[2]), "r"(a[3]), "r"(b0), "r"(b1));
}

__device__ __forceinline__ float tanh_fast(float x) {
    float y;
    asm("tanh.approx.f32 %0, %1;" : "=f"(y) : "f"(x));
    return y;
}
__device__ __forceinline__ float sigmoid_fast(float x) {
    return fmaf(tanh_fast(0.5f * x), 0.5f, 0.5f);
}

// -------- merged conversion prologue: h0 + 3 weight matrices -> fp16 --------
__global__ void cvt_all_kernel(const float4* __restrict__ h0,
                               const float4* __restrict__ w0,
                               const float4* __restrict__ w1,
                               const float4* __restrict__ w2) {
    const size_t nh = (size_t)P_DIM * 2 * B_DIM * H_DIM / 4;
    const size_t nw = (size_t)2048 * 512 / 4;
    const size_t total = nh + 3 * nw;
    for (size_t i = (size_t)blockIdx.x * blockDim.x + threadIdx.x; i < total;
         i += (size_t)gridDim.x * blockDim.x) {
        const float4* src; __half2* dst; size_t j;
        if (i < nh) {
            src = h0; dst = (__half2*)g_h0h; j = i;
        } else {
            const size_t k = i - nh;
            const int sel = (int)(k / nw);
            j = k - (size_t)sel * nw;
            src = (sel == 0) ? w0 : (sel == 1) ? w1 : w2;
            dst = (__half2*)g_w16[sel];
        }
        float4 v = src[j];
        dst[2 * j]     = __floats2half2_rn(v.x, v.y);
        dst[2 * j + 1] = __floats2half2_rn(v.z, v.w);
    }
}

// One LSTM layer, fused GEMM (fp16 mma, fp32 accum) + cell.
// LAYER==0: gates = x@w_ih0^T (IN=2, scalar epilogue) + h0[:,0]@w_hh0^T + b
// LAYER==1: gates = h1@w_ih1^T + h0[:,1]@w_hh1^T + b  (K=1024 concat)
template <int LAYER>
__global__ void __launch_bounds__(256, 2)
lstm_layer_kernel(const float* __restrict__ x_in,
                  const float* __restrict__ c0,
                  const float* __restrict__ w_ih0,
                  const float* __restrict__ b_ih,
                  const float* __restrict__ b_hh,
                  float* __restrict__ d_out) {
    extern __shared__ float smem[];

    const int tid  = threadIdx.x;
    const int warp = tid >> 5;
    const int lane = tid & 31;
    const int wm = warp >> 1;          // 0..3 : 32-row slab
    const int wn = warp & 1;           // 0..1 : 64-col half
    const int rowW = wm * 32;
    const int colW = wn * 64;

    const int mTile = blockIdx.y;      // 0..127
    const int hTile = blockIdx.x;      // 0..15
    const int rowBase = mTile * MT;
    const int hBase   = hTile * HT;

    const int p0 = rowBase >> 8;       // row = p*256 + b
    const int b0 = rowBase & 255;

    // fp16 A operand base pointers (rows contiguous with stride H_DIM)
    const __half* Ab0 = (LAYER == 0)
        ? g_h0h + ((size_t)(p0 * 2 + 0) * B_DIM + b0) * H_DIM
        : g_h1h + (size_t)rowBase * H_DIM;
    const __half* Ab1 = g_h0h + ((size_t)(p0 * 2 + 1) * B_DIM + b0) * H_DIM;
    const __half* Wb0 = (LAYER == 0) ? g_w16[0] : g_w16[1];
    const __half* Wb1 = g_w16[2];

    const int KTILES = (LAYER == 0) ? 8 : 16;   // K/64

    const unsigned smem_u = (unsigned)__cvta_generic_to_shared(smem);
    const uint32_t mb_full  = smem_u + OFF_FULL;
    const uint32_t mb_empty = smem_u + OFF_EMPTY;

    if (tid == 0) {
#pragma unroll
        for (int s = 0; s < NSTAGE; s++) {
            mbar_init(mb_full  + s * 8, 256);   // per-thread cp.async arrivals
            mbar_init(mb_empty + s * 8, 8);     // one arrive per warp
        }
    }
    __syncthreads();

    // -------- stage loader (all 256 threads): waits empty, loads, arrives full ----
    auto load_stage = [&](int kt) {
        int s = kt; while (s >= NSTAGE) s -= NSTAGE;
        const int ip = kt / NSTAGE;
        if (ip >= 1) mbar_wait(mb_empty + s * 8, (uint32_t)((ip + 1) & 1));
        const __half* Ab = (LAYER == 0 || kt < 8) ? Ab0 : Ab1;
        const __half* Wb = (LAYER == 0 || kt < 8) ? Wb0 : Wb1;
        const int kk = (kt & 7) * KTH;
        const unsigned Asd = smem_u + (unsigned)(s * STAGE_B);
        const unsigned Bsd = Asd + (unsigned)A_STAGE_B;
#pragma unroll
        for (int i = 0; i < 4; i++) {
            const int c  = tid + i * 256;       // 0..1023 : 16B chunks
            const int r  = c >> 3;              // 0..127
            const int cc = c & 7;               // chunk within row
            cpa16(Asd + (unsigned)(r * PITCH_B + cc * 16),
                  Ab + (size_t)r * H_DIM + kk + cc * 8);
            const int g = r >> 5, j = r & 31;   // gate-blocked weight row
            cpa16(Bsd + (unsigned)(r * PITCH_B + cc * 16),
                  Wb + (size_t)(g * H_DIM + hBase + j) * H_DIM + kk + cc * 8);
        }
        cpasync_arrive(mb_full + s * 8);
    };

    float acc[2][8][4];
#pragma unroll
    for (int mi = 0; mi < 2; mi++)
#pragma unroll
        for (int nt = 0; nt < 8; nt++)
#pragma unroll
            for (int q = 0; q < 4; q++) acc[mi][nt][q] = 0.0f;

    // -------- per-thread LDSM base offsets (bytes) --------
    const int m8 = lane >> 3;
    const int l8 = lane & 7;
    const uint32_t aoff =
        (uint32_t)((rowW + (m8 & 1) * 8 + l8) * PITCH_B + (m8 >> 1) * 16);
    uint32_t boff[4];
#pragma unroll
    for (int t = 0; t < 4; t++)
        boff[t] = (uint32_t)((colW + (t * 2 + (m8 >> 1)) * 8 + l8) * PITCH_B
                             + (m8 & 1) * 16);

    // -------- mainloop: free-running mbarrier pipeline (no CTA barrier) --------
    load_stage(0);
    load_stage(1);

    int s = 0;
    for (int kt = 0; kt < KTILES; kt++) {
        const int cyc = kt / NSTAGE;
        mbar_wait(mb_full + s * 8, (uint32_t)(cyc & 1));

        const uint32_t As = smem_u + (uint32_t)(s * STAGE_B);
        const uint32_t Bs = As + (uint32_t)A_STAGE_B;

        // initial fragment loads for this k-tile
        uint32_t afr[2][8], bfr[2][4];
        ldsm4(&afr[0][0], As + aoff);
        ldsm4(&afr[0][4], As + aoff + (uint32_t)(16 * PITCH_B));
        ldsm4(bfr[0], Bs + boff[0]);

        int cur = 0;
#pragma unroll
        for (int k0 = 0; k0 < 4; k0++) {
#pragma unroll
            for (int t = 0; t < 4; t++) {
                if (t < 3) {
                    ldsm4(bfr[(t + 1) & 1], Bs + boff[t + 1] + k0 * 32);
                } else if (k0 < 3) {
                    ldsm4(&afr[cur ^ 1][0], As + aoff + (k0 + 1) * 32);
                    ldsm4(&afr[cur ^ 1][4],
                          As + aoff + (uint32_t)(16 * PITCH_B) + (k0 + 1) * 32);
                    ldsm4(bfr[0], Bs + boff[0] + (k0 + 1) * 32);
                }
                const uint32_t* b = bfr[t & 1];
                mma_f16(acc[0][2 * t],     &afr[cur][0], b[0], b[1]);
                mma_f16(acc[1][2 * t],     &afr[cur][4], b[0], b[1]);
                mma_f16(acc[0][2 * t + 1], &afr[cur][0], b[2], b[3]);
                mma_f16(acc[1][2 * t + 1], &afr[cur][4], b[2], b[3]);
            }
            cur ^= 1;
        }

        if (lane == 0) mbar_arrive(mb_empty + s * 8);   // this warp done with stage
        if (kt + 2 < KTILES) load_stage(kt + 2);

        if (++s == NSTAGE) s = 0;
    }
    __syncthreads();   // all warps past mainloop; stage smem reusable for G

    // -------- epilogue: gates -> smem (overlay pipeline buffers) --------
    float* G = smem;  // [128][GP], col index = gate*32 + j
#pragma unroll
    for (int mi = 0; mi < 2; mi++) {
#pragma unroll
        for (int nt = 0; nt < 8; nt++) {
            const int r  = rowW + mi * 16 + (lane >> 2);
            const int cC = colW + nt * 8 + 2 * (lane & 3);
            G[r * GP + cC]           = acc[mi][nt][0];
            G[r * GP + cC + 1]       = acc[mi][nt][1];
            G[(r + 8) * GP + cC]     = acc[mi][nt][2];
            G[(r + 8) * GP + cC + 1] = acc[mi][nt][3];
        }
    }
    __syncthreads();

    // -------- LSTM cell + stores --------
    const size_t hn_off = (size_t)PB * H_DIM;
    const size_t cn_off = hn_off + (size_t)P_DIM * 2 * B_DIM * H_DIM;

    const int j = tid & 31;
    const int h = hBase + j;
    const float bi = b_ih[h]             + b_hh[h];
    const float bf = b_ih[H_DIM + h]     + b_hh[H_DIM + h];
    const float bg = b_ih[2 * H_DIM + h] + b_hh[2 * H_DIM + h];
    const float bo = b_ih[3 * H_DIM + h] + b_hh[3 * H_DIM + h];
    float wi0 = 0.f, wi1 = 0.f, wf0 = 0.f, wf1 = 0.f, wg0 = 0.f, wg1 = 0.f, wo0 = 0.f, wo1 = 0.f;
    if (LAYER == 0) {
        wi0 = w_ih0[(size_t)h * 2];                    wi1 = w_ih0[(size_t)h * 2 + 1];
        wf0 = w_ih0[(size_t)(H_DIM + h) * 2];          wf1 = w_ih0[(size_t)(H_DIM + h) * 2 + 1];
        wg0 = w_ih0[(size_t)(2 * H_DIM + h) * 2];      wg1 = w_ih0[(size_t)(2 * H_DIM + h) * 2 + 1];
        wo0 = w_ih0[(size_t)(3 * H_DIM + h) * 2];      wo1 = w_ih0[(size_t)(3 * H_DIM + h) * 2 + 1];
    }

#pragma unroll 4
    for (int it = 0; it < 16; it++) {             // r covers 0..127
        const int r   = (tid >> 5) + it * 8;
        const int row = rowBase + r;
        const int p   = row >> 8;
        const int b   = row & 255;

        float gi = G[r * GP + j]      + bi;
        float gf = G[r * GP + 32 + j] + bf;
        float gg = G[r * GP + 64 + j] + bg;
        float go = G[r * GP + 96 + j] + bo;

        if (LAYER == 0) {
            const float x0 = x_in[(size_t)(b * P_DIM + p) * IN_DIM];
            const float x1 = x_in[(size_t)(b * P_DIM + p) * IN_DIM + 1];
            gi += x0 * wi0 + x1 * wi1;
            gf += x0 * wf0 + x1 * wf1;
            gg += x0 * wg0 + x1 * wg1;
            go += x0 * wo0 + x1 * wo1;
        }

        const float i_s = sigmoid_fast(gi);
        const float f_s = sigmoid_fast(gf);
        const float o_s = sigmoid_fast(go);
        const float g_t = tanh_fast(gg);

        const size_t cidx = (((size_t)p * 2 + LAYER) * B_DIM + b) * H_DIM + h;
        const float c_new = f_s * c0[cidx] + i_s * g_t;
        const float h_new = o_s * tanh_fast(c_new);

        d_out[hn_off + cidx] = h_new;
        d_out[cn_off + cidx] = c_new;
        if (LAYER == 0) {
            g_h1h[(size_t)row * H_DIM + h] = __float2half_rn(h_new);
        } else {
            d_out[((size_t)b * P_DIM + p) * H_DIM + h] = h_new;  // out[b,p,h]
        }
    }
}

extern "C" void kernel_launch(void* const* d_in, const int* in_sizes, int n_in,
                              void* d_out, int out_size) {
    const float* x     = (const float*)d_in[0];   // input_traces [B,P,2]
    const float* h0    = (const float*)d_in[1];   // [P,L,B,H]
    const float* c0    = (const float*)d_in[2];   // [P,L,B,H]
    const float* w_ih0 = (const float*)d_in[3];   // [2048,2]
    const float* w_hh0 = (const float*)d_in[4];   // [2048,512]
    const float* b_ih0 = (const float*)d_in[5];
    const float* b_hh0 = (const float*)d_in[6];
    const float* w_ih1 = (const float*)d_in[7];   // [2048,512]
    const float* w_hh1 = (const float*)d_in[8];   // [2048,512]
    const float* b_ih1 = (const float*)d_in[9];
    const float* b_hh1 = (const float*)d_in[10];
    float* out = (float*)d_out;

    // prologue: fp32 -> fp16 conversions (single merged kernel)
    cvt_all_kernel<<<4096, 256>>>((const float4*)h0, (const float4*)w_hh0,
                                  (const float4*)w_ih1, (const float4*)w_hh1);

    cudaFuncSetAttribute(lstm_layer_kernel<0>,
                         cudaFuncAttributeMaxDynamicSharedMemorySize, SMEM_TOTAL);
    cudaFuncSetAttribute(lstm_layer_kernel<1>,
                         cudaFuncAttributeMaxDynamicSharedMemorySize, SMEM_TOTAL);

    dim3 grid(H_DIM / HT, PB / MT);               // (16, 128)
    lstm_layer_kernel<0><<<grid, 256, SMEM_TOTAL>>>(x, c0, w_ih0, b_ih0, b_hh0, out);
    lstm_layer_kernel<1><<<grid, 256, SMEM_TOTAL>>>(nullptr, c0, nullptr,
                                                    b_ih1, b_hh1, out);
}